// round 15
// baseline (speedup 1.0000x reference)
#include <cuda_runtime.h>
#include <cuda_fp16.h>
#include <stdint.h>
#include <math.h>

#define Tn 4096
#define Hn 1024
#define En 8
#define In 1024
#define NCTAS 304   // 2 per SM (152 SMs on GB300)

// ==================== scratch ====================
__device__ int   g_cnt[En];
__device__ float g_imp[En];
__device__ int   g_stok[En * Tn];     // slot -> token
__device__ float g_swt [En * Tn];     // slot -> combine weight
__device__ __align__(16) __half g_wgf[(size_t)En * Hn * In];
__device__ __align__(16) __half g_wuf[(size_t)En * Hn * In];
__device__ __align__(16) __half g_wdf[(size_t)En * In * Hn];
__device__ __align__(16) __half g_xa[(size_t)En * Tn * Hn];
__device__ __align__(16) __half g_ih[(size_t)En * Tn * In];

// ==================== helpers ====================
__device__ __forceinline__ uint32_t smem_u32(const void* p) {
    uint32_t a;
    asm("{ .reg .u64 t; cvta.to.shared.u64 t, %1; cvt.u32.u64 %0, t; }" : "=r"(a) : "l"(p));
    return a;
}
__device__ __forceinline__ void cpa16(uint32_t dst, const void* src) {
    asm volatile("cp.async.cg.shared.global [%0], [%1], 16;" :: "r"(dst), "l"(src));
}
#define CP_COMMIT() asm volatile("cp.async.commit_group;" ::: "memory")
#define CP_WAIT2()  asm volatile("cp.async.wait_group 2;" ::: "memory")

#define LDM4(r, addr)                                                          \
    asm volatile("ldmatrix.sync.aligned.m8n8.x4.shared.b16 {%0,%1,%2,%3}, [%4];" \
        : "=r"((r)[0]), "=r"((r)[1]), "=r"((r)[2]), "=r"((r)[3]) : "r"(addr))

#define LDM4T(r, addr)                                                         \
    asm volatile("ldmatrix.sync.aligned.m8n8.x4.trans.shared.b16 {%0,%1,%2,%3}, [%4];" \
        : "=r"((r)[0]), "=r"((r)[1]), "=r"((r)[2]), "=r"((r)[3]) : "r"(addr))

#define MMA(d, a, b0, b1)                                                      \
    asm volatile("mma.sync.aligned.m16n8k16.row.col.f32.f16.f16.f32 "          \
        "{%0,%1,%2,%3}, {%4,%5,%6,%7}, {%8,%9}, {%0,%1,%2,%3};"                \
        : "+f"((d)[0]), "+f"((d)[1]), "+f"((d)[2]), "+f"((d)[3])               \
        : "r"((a)[0]), "r"((a)[1]), "r"((a)[2]), "r"((a)[3]), "r"(b0), "r"(b1))

__device__ __forceinline__ uint32_t pack2h(float a, float b) {
    __half2 H = __floats2half2_rn(a, b);
    return *(uint32_t*)&H;
}

// ==================== small kernels ====================
__global__ void init_kernel(float* out, int n) {
    int i = blockIdx.x * 256 + threadIdx.x;
    if (i < n) out[i] = 0.0f;
    if (blockIdx.x == 0 && threadIdx.x < En) {
        g_cnt[threadIdx.x] = 0;  g_imp[threadIdx.x] = 0.0f;
    }
}

// router + fused gather
__global__ void router_kernel(const float* __restrict__ x, const float* __restrict__ Wr) {
    int t = blockIdx.x;
    int warp = threadIdx.x >> 5, lane = threadIdx.x & 31;
    const float* xt = x + (size_t)t * Hn;
    float acc = 0.0f;
    for (int h = lane; h < Hn; h += 32) acc += xt[h] * Wr[h * En + warp];
    #pragma unroll
    for (int o = 16; o > 0; o >>= 1) acc += __shfl_xor_sync(0xffffffff, acc, o);
    __shared__ float logits[En];
    __shared__ int   sSlot[2];
    if (lane == 0) logits[warp] = acc;
    __syncthreads();
    if (threadIdx.x == 0) {
        float mx = logits[0];
        #pragma unroll
        for (int e = 1; e < En; e++) mx = fmaxf(mx, logits[e]);
        float p[En], s = 0.0f;
        #pragma unroll
        for (int e = 0; e < En; e++) { p[e] = expf(logits[e] - mx); s += p[e]; }
        float inv = 1.0f / s;
        #pragma unroll
        for (int e = 0; e < En; e++) { p[e] *= inv; atomicAdd(&g_imp[e], p[e]); }
        int i0 = 0;
        #pragma unroll
        for (int e = 1; e < En; e++) if (p[e] > p[i0]) i0 = e;
        int i1 = (i0 == 0) ? 1 : 0;
        #pragma unroll
        for (int e = 0; e < En; e++) if (e != i0 && p[e] > p[i1]) i1 = e;
        float w0 = p[i0], w1 = p[i1];
        float sw = fmaxf(w0 + w1, 1e-9f);
        w0 /= sw; w1 /= sw;
        int p0 = atomicAdd(&g_cnt[i0], 1);
        int p1 = atomicAdd(&g_cnt[i1], 1);
        int s0 = i0 * Tn + p0, s1 = i1 * Tn + p1;
        g_stok[s0] = t;  g_swt[s0] = w0;
        g_stok[s1] = t;  g_swt[s1] = w1;
        sSlot[0] = s0;  sSlot[1] = s1;
    }
    __syncthreads();
    int i = threadIdx.x;
    float4 v = *(const float4*)(xt + i * 4);
    uint2 hv = make_uint2(pack2h(v.x, v.y), pack2h(v.z, v.w));
    *(uint2*)(g_xa + (size_t)sSlot[0] * Hn + i * 4) = hv;
    *(uint2*)(g_xa + (size_t)sSlot[1] * Hn + i * 4) = hv;
}

__global__ void aux_kernel(float* out, int aux_idx) {
    if (threadIdx.x == 0) {
        float s = 0.0f;
        #pragma unroll
        for (int e = 0; e < En; e++)
            s += ((float)g_cnt[e] / (float)Tn) * (g_imp[e] / (float)Tn);
        out[aux_idx] = (float)En * s * 0.01f;
    }
}

__global__ void wconv_kernel(const float* __restrict__ Wg,
                             const float* __restrict__ Wu,
                             const float* __restrict__ Wd) {
    int z = blockIdx.y;
    const float* src = (z == 0) ? Wg : (z == 1) ? Wu : Wd;
    __half* dst = (z == 0) ? g_wgf : (z == 1) ? g_wuf : g_wdf;
    size_t i = ((size_t)blockIdx.x * 256 + threadIdx.x) * 4;
    float4 v = *(const float4*)(src + i);
    uint32_t h0 = pack2h(v.x, v.y), h1 = pack2h(v.z, v.w);
    *(uint2*)(dst + i) = make_uint2(h0, h1);
}

// ==================== smem layout (BK=32, 4-stage cp.async) ====================
#define A_ROWB 80
#define A_ARR (128 * A_ROWB)     // 10240
#define BT_ROWB 144
#define BT_ARR (32 * BT_ROWB)    // 4608
#define B2_ROWB 272
#define B2_ARR (32 * B2_ROWB)    // 8704
#define G1_STG (A_ARR + 2 * BT_ARR)   // 19456
#define G1_SMEM (4 * G1_STG)          // 77824
#define G2_STG (A_ARR + B2_ARR)       // 18944
#define G2_SMEM (4 * G2_STG)          // 75776

// ==================== GEMM1: persistent tiles, CTA 128x64(G)+64(U) ====================
__global__ __launch_bounds__(512, 2)
void gemm1_kernel() {
    extern __shared__ char smem[];
    uint32_t sb = smem_u32(smem);
    int tid = threadIdx.x, wid = tid >> 5, lane = tid & 31;
    int wm = wid & 3, wn = wid >> 2;
    int ar = lane & 15, ac = lane >> 4;
    int karow = lane & 15, kacol = lane >> 4;

    int fArow = tid >> 2, fAch = tid & 3;
    int isU = tid >= 256;
    int wt = tid & 255;
    int fWrow = wt >> 3, fWch = wt & 7;

    // total tiles across experts: ceil(cnt/128)*16 each
    int total = 0;
    #pragma unroll
    for (int e = 0; e < En; e++) total += ((g_cnt[e] + 127) >> 7) * 16;

    for (int tile = blockIdx.x; tile < total; tile += gridDim.x) {
        // decode (e, mBlk, nBlk)
        int rem = tile, e = 0;
        while (true) {
            int te = ((g_cnt[e] + 127) >> 7) * 16;
            if (rem < te) break;
            rem -= te;  e++;
        }
        int mBase = (rem >> 4) * 128;
        int n0 = (rem & 15) * 64;
        int n_rows = g_cnt[e];

        const __half* Asrc = g_xa + ((size_t)(e * Tn + mBase + fArow)) * Hn + fAch * 8;
        uint32_t adst = fArow * A_ROWB + fAch * 16;
        const __half* Wsrc = (isU ? g_wuf : g_wgf) + ((size_t)e * Hn + fWrow) * In + n0 + fWch * 8;
        uint32_t wdst = A_ARR + (isU ? BT_ARR : 0) + fWrow * BT_ROWB + fWch * 16;

        #define G1_FILL(s)                                                     \
            do {                                                               \
                uint32_t st = sb + ((s) & 3) * G1_STG;                         \
                int k0 = (s) * 32;                                             \
                cpa16(st + adst, Asrc + k0);                                   \
                cpa16(st + wdst, Wsrc + (size_t)k0 * In);                      \
            } while (0)

        float aG[2][2][4] = {{{0}}}, aU[2][2][4] = {{{0}}};

        G1_FILL(0); CP_COMMIT();
        G1_FILL(1); CP_COMMIT();
        G1_FILL(2); CP_COMMIT();

        #pragma unroll 1
        for (int s = 0; s < 32; s++) {
            CP_WAIT2();
            __syncthreads();
            if (s + 3 < 32) G1_FILL(s + 3);
            CP_COMMIT();

            uint32_t aBase = sb + (s & 3) * G1_STG;
            uint32_t gBase = aBase + A_ARR;
            #pragma unroll
            for (int kk = 0; kk < 2; kk++) {
                uint32_t ah[2][4];
                #pragma unroll
                for (int mt = 0; mt < 2; mt++) {
                    uint32_t ad = aBase + (uint32_t)(wm * 32 + mt * 16 + ar) * A_ROWB + kk * 32 + ac * 16;
                    LDM4(ah[mt], ad);
                }
                uint32_t bg[4], bu[4];
                {
                    uint32_t bd = gBase + (uint32_t)(kk * 16 + karow) * BT_ROWB + wn * 32 + kacol * 16;
                    LDM4T(bg, bd);
                    LDM4T(bu, bd + BT_ARR);
                }
                #pragma unroll
                for (int mt = 0; mt < 2; mt++)
                    #pragma unroll
                    for (int nt = 0; nt < 2; nt++) {
                        int p = nt * 2;
                        MMA(aG[mt][nt], ah[mt], bg[p], bg[p + 1]);
                        MMA(aU[mt][nt], ah[mt], bu[p], bu[p + 1]);
                    }
            }
        }
        #undef G1_FILL

        // epilogue: silu(g)*u -> fp16 intermediate
        #pragma unroll
        for (int mt = 0; mt < 2; mt++) {
            #pragma unroll
            for (int nt = 0; nt < 2; nt++) {
                int c = n0 + wn * 16 + nt * 8 + (lane & 3) * 2;
                #pragma unroll
                for (int h = 0; h < 2; h++) {
                    int r = mBase + wm * 32 + mt * 16 + (lane >> 2) + h * 8;
                    if (r < n_rows) {
                        float g0 = aG[mt][nt][h * 2],     u0 = aU[mt][nt][h * 2];
                        float g1 = aG[mt][nt][h * 2 + 1], u1 = aU[mt][nt][h * 2 + 1];
                        float i0 = u0 * g0 / (1.0f + __expf(-g0));
                        float i1 = u1 * g1 / (1.0f + __expf(-g1));
                        size_t o = ((size_t)e * Tn + r) * In + c;
                        *(uint32_t*)(g_ih + o) = pack2h(i0, i1);
                    }
                }
            }
        }
    }
}

// ==================== GEMM2: persistent tiles, CTA 128x128, atomic scatter ====================
__global__ __launch_bounds__(512, 2)
void gemm2_kernel(float* __restrict__ out) {
    extern __shared__ char smem[];
    uint32_t sb = smem_u32(smem);
    int tid = threadIdx.x, wid = tid >> 5, lane = tid & 31;
    int wm = wid & 3, wn = wid >> 2;
    int ar = lane & 15, ac = lane >> 4;
    int karow = lane & 15, kacol = lane >> 4;

    int fArow = tid >> 2, fAch = tid & 3;
    int fBrow = tid >> 4, fBch = tid & 15;

    int total = 0;
    #pragma unroll
    for (int e = 0; e < En; e++) total += ((g_cnt[e] + 127) >> 7) * 8;

    for (int tile = blockIdx.x; tile < total; tile += gridDim.x) {
        int rem = tile, e = 0;
        while (true) {
            int te = ((g_cnt[e] + 127) >> 7) * 8;
            if (rem < te) break;
            rem -= te;  e++;
        }
        int mBase = (rem >> 3) * 128;
        int n0 = (rem & 7) * 128;
        int n_rows = g_cnt[e];

        const __half* Asrc = g_ih + ((size_t)(e * Tn + mBase + fArow)) * In + fAch * 8;
        uint32_t adst = fArow * A_ROWB + fAch * 16;
        const __half* Bsrc = g_wdf + ((size_t)e * In + fBrow) * Hn + n0 + fBch * 8;
        uint32_t bdst = A_ARR + fBrow * B2_ROWB + fBch * 16;

        #define G2_FILL(s)                                                     \
            do {                                                               \
                uint32_t st = sb + ((s) & 3) * G2_STG;                         \
                int k0 = (s) * 32;                                             \
                cpa16(st + adst, Asrc + k0);                                   \
                cpa16(st + bdst, Bsrc + (size_t)k0 * Hn);                      \
            } while (0)

        float acc[2][4][4] = {{{0}}};

        G2_FILL(0); CP_COMMIT();
        G2_FILL(1); CP_COMMIT();
        G2_FILL(2); CP_COMMIT();

        #pragma unroll 1
        for (int s = 0; s < 32; s++) {
            CP_WAIT2();
            __syncthreads();
            if (s + 3 < 32) G2_FILL(s + 3);
            CP_COMMIT();

            uint32_t aBase = sb + (s & 3) * G2_STG;
            uint32_t bBase = aBase + A_ARR;
            #pragma unroll
            for (int kk = 0; kk < 2; kk++) {
                uint32_t ah[2][4];
                #pragma unroll
                for (int mt = 0; mt < 2; mt++) {
                    uint32_t ad = aBase + (uint32_t)(wm * 32 + mt * 16 + ar) * A_ROWB + kk * 32 + ac * 16;
                    LDM4(ah[mt], ad);
                }
                uint32_t bh[2][4];
                #pragma unroll
                for (int ng = 0; ng < 2; ng++) {
                    uint32_t bd = bBase + (uint32_t)(kk * 16 + karow) * B2_ROWB
                                  + wn * 64 + ng * 32 + kacol * 16;
                    LDM4T(bh[ng], bd);
                }
                #pragma unroll
                for (int mt = 0; mt < 2; mt++)
                    #pragma unroll
                    for (int nt = 0; nt < 4; nt++) {
                        int ng = nt >> 1, p = (nt & 1) * 2;
                        MMA(acc[mt][nt], ah[mt], bh[ng][p], bh[ng][p + 1]);
                    }
            }
        }
        #undef G2_FILL

        // epilogue: weighted atomic scatter into out
        #pragma unroll
        for (int mt = 0; mt < 2; mt++) {
            #pragma unroll
            for (int h = 0; h < 2; h++) {
                int r = mBase + wm * 32 + mt * 16 + (lane >> 2) + h * 8;
                if (r < n_rows) {
                    int tok  = g_stok[e * Tn + r];
                    float w  = g_swt [e * Tn + r];
                    float* dst = out + (size_t)tok * Hn;
                    #pragma unroll
                    for (int nt = 0; nt < 4; nt++) {
                        int c = n0 + wn * 32 + nt * 8 + (lane & 3) * 2;
                        atomicAdd(dst + c,     w * acc[mt][nt][h * 2]);
                        atomicAdd(dst + c + 1, w * acc[mt][nt][h * 2 + 1]);
                    }
                }
            }
        }
    }
}

// ==================== launch ====================
extern "C" void kernel_launch(void* const* d_in, const int* in_sizes, int n_in,
                              void* d_out, int out_size) {
    const float* x  = (const float*)d_in[0];
    const float* Wr = (const float*)d_in[1];
    const float* Wg = (const float*)d_in[2];
    const float* Wu = (const float*)d_in[3];
    const float* Wd = (const float*)d_in[4];
    float* out = (float*)d_out;

    cudaFuncSetAttribute(gemm1_kernel, cudaFuncAttributeMaxDynamicSharedMemorySize, G1_SMEM);
    cudaFuncSetAttribute(gemm2_kernel, cudaFuncAttributeMaxDynamicSharedMemorySize, G2_SMEM);

    init_kernel<<<(out_size + 255) / 256, 256>>>(out, out_size);

    dim3 wg((En * Hn * In / 4) / 256, 3);
    wconv_kernel<<<wg, 256>>>(Wg, Wu, Wd);

    router_kernel<<<Tn, 256>>>(x, Wr);
    if (out_size > Tn * Hn)
        aux_kernel<<<1, 32>>>(out, Tn * Hn);

    gemm1_kernel<<<NCTAS, 512, G1_SMEM>>>();
    gemm2_kernel<<<NCTAS, 512, G2_SMEM>>>(out);
}

// round 16
// speedup vs baseline: 1.0107x; 1.0107x over previous
#include <cuda_runtime.h>
#include <cuda_fp16.h>
#include <stdint.h>
#include <math.h>

#define Tn 4096
#define Hn 1024
#define En 8
#define In 1024

// ==================== scratch ====================
__device__ int   g_cnt[En];
__device__ float g_imp[En];
__device__ int   g_stok[En * Tn];     // slot -> token
__device__ float g_swt [En * Tn];     // slot -> combine weight
__device__ __align__(16) __half g_wgf[(size_t)En * Hn * In];
__device__ __align__(16) __half g_wuf[(size_t)En * Hn * In];
__device__ __align__(16) __half g_wdf[(size_t)En * In * Hn];
__device__ __align__(16) __half g_xa[(size_t)En * Tn * Hn];
__device__ __align__(16) __half g_ih[(size_t)En * Tn * In];

// ==================== helpers ====================
__device__ __forceinline__ uint32_t smem_u32(const void* p) {
    uint32_t a;
    asm("{ .reg .u64 t; cvta.to.shared.u64 t, %1; cvt.u32.u64 %0, t; }" : "=r"(a) : "l"(p));
    return a;
}
__device__ __forceinline__ void cpa16(uint32_t dst, const void* src) {
    asm volatile("cp.async.cg.shared.global [%0], [%1], 16;" :: "r"(dst), "l"(src));
}
#define CP_COMMIT() asm volatile("cp.async.commit_group;" ::: "memory")
#define CP_WAIT2()  asm volatile("cp.async.wait_group 2;" ::: "memory")

#define LDM4(r, addr)                                                          \
    asm volatile("ldmatrix.sync.aligned.m8n8.x4.shared.b16 {%0,%1,%2,%3}, [%4];" \
        : "=r"((r)[0]), "=r"((r)[1]), "=r"((r)[2]), "=r"((r)[3]) : "r"(addr))

#define LDM4T(r, addr)                                                         \
    asm volatile("ldmatrix.sync.aligned.m8n8.x4.trans.shared.b16 {%0,%1,%2,%3}, [%4];" \
        : "=r"((r)[0]), "=r"((r)[1]), "=r"((r)[2]), "=r"((r)[3]) : "r"(addr))

#define MMA(d, a, b0, b1)                                                      \
    asm volatile("mma.sync.aligned.m16n8k16.row.col.f32.f16.f16.f32 "          \
        "{%0,%1,%2,%3}, {%4,%5,%6,%7}, {%8,%9}, {%0,%1,%2,%3};"                \
        : "+f"((d)[0]), "+f"((d)[1]), "+f"((d)[2]), "+f"((d)[3])               \
        : "r"((a)[0]), "r"((a)[1]), "r"((a)[2]), "r"((a)[3]), "r"(b0), "r"(b1))

__device__ __forceinline__ uint32_t pack2h(float a, float b) {
    __half2 H = __floats2half2_rn(a, b);
    return *(uint32_t*)&H;
}

// ==================== wconv + init (fused): cast weights, zero out + counters ====================
__global__ void wconv_kernel(const float* __restrict__ Wg,
                             const float* __restrict__ Wu,
                             const float* __restrict__ Wd,
                             float* __restrict__ out, int out_n) {
    int z = blockIdx.y;
    const float* src = (z == 0) ? Wg : (z == 1) ? Wu : Wd;
    __half* dst = (z == 0) ? g_wgf : (z == 1) ? g_wuf : g_wdf;
    size_t i = ((size_t)blockIdx.x * 256 + threadIdx.x) * 4;
    float4 v = *(const float4*)(src + i);
    uint32_t h0 = pack2h(v.x, v.y), h1 = pack2h(v.z, v.w);
    *(uint2*)(dst + i) = make_uint2(h0, h1);

    if (z == 0) {
        // zero output: 262144 threads x up to 17 floats covers out_n (<= Tn*Hn+1)
        int t = blockIdx.x * 256 + threadIdx.x;
        #pragma unroll
        for (int j = 0; j < 4; j++) {
            int o = (j * 262144 + t) * 4;
            if (o + 3 < out_n) *(float4*)(out + o) = make_float4(0.f, 0.f, 0.f, 0.f);
        }
        // tail elements (out_n may be Tn*Hn+1)
        int tail_base = 4194304;  // 4*262144*4
        int o = tail_base + t;
        if (o < out_n) out[o] = 0.0f;
        if (blockIdx.x == 0 && threadIdx.x < En) {
            g_cnt[threadIdx.x] = 0;  g_imp[threadIdx.x] = 0.0f;
        }
    }
}

// ==================== router + fused gather ====================
__global__ void router_kernel(const float* __restrict__ x, const float* __restrict__ Wr) {
    int t = blockIdx.x;
    int warp = threadIdx.x >> 5, lane = threadIdx.x & 31;
    const float* xt = x + (size_t)t * Hn;
    float acc = 0.0f;
    for (int h = lane; h < Hn; h += 32) acc += xt[h] * Wr[h * En + warp];
    #pragma unroll
    for (int o = 16; o > 0; o >>= 1) acc += __shfl_xor_sync(0xffffffff, acc, o);
    __shared__ float logits[En];
    __shared__ int   sSlot[2];
    if (lane == 0) logits[warp] = acc;
    __syncthreads();
    if (threadIdx.x == 0) {
        float mx = logits[0];
        #pragma unroll
        for (int e = 1; e < En; e++) mx = fmaxf(mx, logits[e]);
        float p[En], s = 0.0f;
        #pragma unroll
        for (int e = 0; e < En; e++) { p[e] = expf(logits[e] - mx); s += p[e]; }
        float inv = 1.0f / s;
        #pragma unroll
        for (int e = 0; e < En; e++) { p[e] *= inv; atomicAdd(&g_imp[e], p[e]); }
        int i0 = 0;
        #pragma unroll
        for (int e = 1; e < En; e++) if (p[e] > p[i0]) i0 = e;
        int i1 = (i0 == 0) ? 1 : 0;
        #pragma unroll
        for (int e = 0; e < En; e++) if (e != i0 && p[e] > p[i1]) i1 = e;
        float w0 = p[i0], w1 = p[i1];
        float sw = fmaxf(w0 + w1, 1e-9f);
        w0 /= sw; w1 /= sw;
        int p0 = atomicAdd(&g_cnt[i0], 1);
        int p1 = atomicAdd(&g_cnt[i1], 1);
        int s0 = i0 * Tn + p0, s1 = i1 * Tn + p1;
        g_stok[s0] = t;  g_swt[s0] = w0;
        g_stok[s1] = t;  g_swt[s1] = w1;
        sSlot[0] = s0;  sSlot[1] = s1;
    }
    __syncthreads();
    int i = threadIdx.x;
    float4 v = *(const float4*)(xt + i * 4);
    uint2 hv = make_uint2(pack2h(v.x, v.y), pack2h(v.z, v.w));
    *(uint2*)(g_xa + (size_t)sSlot[0] * Hn + i * 4) = hv;
    *(uint2*)(g_xa + (size_t)sSlot[1] * Hn + i * 4) = hv;
}

// ==================== smem layout (BK=32, 4-stage cp.async) ====================
#define A_ROWB 80
#define A_ARR (128 * A_ROWB)     // 10240
#define BT_ROWB 144
#define BT_ARR (32 * BT_ROWB)    // 4608
#define B2_ROWB 272
#define B2_ARR (32 * B2_ROWB)    // 8704
#define G1_STG (A_ARR + 2 * BT_ARR)   // 19456
#define G1_SMEM (4 * G1_STG)          // 77824
#define G2_STG (A_ARR + B2_ARR)       // 18944
#define G2_SMEM (4 * G2_STG)          // 75776

// ==================== GEMM1: CTA 128x64(G)+64(U), 16 warps 4x4, warp 32x16 ====================
// also computes aux loss (fused) in grid block (0,0,0)
__global__ __launch_bounds__(512, 2)
void gemm1_kernel(float* __restrict__ out, int do_aux) {
    extern __shared__ char smem[];
    // fused aux loss (g_cnt/g_imp final after router)
    if (do_aux && blockIdx.x == 0 && blockIdx.y == 0 && blockIdx.z == 0 && threadIdx.x == 0) {
        float s = 0.0f;
        #pragma unroll
        for (int e = 0; e < En; e++)
            s += ((float)g_cnt[e] / (float)Tn) * (g_imp[e] / (float)Tn);
        out[Tn * Hn] = (float)En * s * 0.01f;
    }

    int e = blockIdx.z;
    int n_rows = g_cnt[e];
    int mBase = blockIdx.y * 128;
    if (mBase >= n_rows) return;
    int n0 = blockIdx.x * 64;

    uint32_t sb = smem_u32(smem);
    int tid = threadIdx.x, wid = tid >> 5, lane = tid & 31;
    int wm = wid & 3, wn = wid >> 2;
    int ar = lane & 15, ac = lane >> 4;
    int karow = lane & 15, kacol = lane >> 4;

    int fArow = tid >> 2, fAch = tid & 3;
    const __half* Asrc = g_xa + ((size_t)(e * Tn + mBase + fArow)) * Hn + fAch * 8;
    uint32_t adst = fArow * A_ROWB + fAch * 16;
    int isU = tid >= 256;
    int wt = tid & 255;
    int fWrow = wt >> 3, fWch = wt & 7;
    const __half* Wsrc = (isU ? g_wuf : g_wgf) + ((size_t)e * Hn + fWrow) * In + n0 + fWch * 8;
    uint32_t wdst = A_ARR + (isU ? BT_ARR : 0) + fWrow * BT_ROWB + fWch * 16;

    #define G1_FILL(s)                                                         \
        do {                                                                   \
            uint32_t st = sb + ((s) & 3) * G1_STG;                             \
            int k0 = (s) * 32;                                                 \
            cpa16(st + adst, Asrc + k0);                                       \
            cpa16(st + wdst, Wsrc + (size_t)k0 * In);                          \
        } while (0)

    float aG[2][2][4] = {{{0}}}, aU[2][2][4] = {{{0}}};

    G1_FILL(0); CP_COMMIT();
    G1_FILL(1); CP_COMMIT();
    G1_FILL(2); CP_COMMIT();

    #pragma unroll 1
    for (int s = 0; s < 32; s++) {
        CP_WAIT2();
        __syncthreads();
        if (s + 3 < 32) G1_FILL(s + 3);
        CP_COMMIT();

        uint32_t aBase = sb + (s & 3) * G1_STG;
        uint32_t gBase = aBase + A_ARR;
        #pragma unroll
        for (int kk = 0; kk < 2; kk++) {
            uint32_t ah[2][4];
            #pragma unroll
            for (int mt = 0; mt < 2; mt++) {
                uint32_t ad = aBase + (uint32_t)(wm * 32 + mt * 16 + ar) * A_ROWB + kk * 32 + ac * 16;
                LDM4(ah[mt], ad);
            }
            uint32_t bg[4], bu[4];
            {
                uint32_t bd = gBase + (uint32_t)(kk * 16 + karow) * BT_ROWB + wn * 32 + kacol * 16;
                LDM4T(bg, bd);
                LDM4T(bu, bd + BT_ARR);
            }
            #pragma unroll
            for (int mt = 0; mt < 2; mt++)
                #pragma unroll
                for (int nt = 0; nt < 2; nt++) {
                    int p = nt * 2;
                    MMA(aG[mt][nt], ah[mt], bg[p], bg[p + 1]);
                    MMA(aU[mt][nt], ah[mt], bu[p], bu[p + 1]);
                }
        }
    }

    // epilogue: silu(g)*u -> fp16 intermediate
    #pragma unroll
    for (int mt = 0; mt < 2; mt++) {
        #pragma unroll
        for (int nt = 0; nt < 2; nt++) {
            int c = n0 + wn * 16 + nt * 8 + (lane & 3) * 2;
            #pragma unroll
            for (int h = 0; h < 2; h++) {
                int r = mBase + wm * 32 + mt * 16 + (lane >> 2) + h * 8;
                if (r < n_rows) {
                    float g0 = aG[mt][nt][h * 2],     u0 = aU[mt][nt][h * 2];
                    float g1 = aG[mt][nt][h * 2 + 1], u1 = aU[mt][nt][h * 2 + 1];
                    float i0 = u0 * g0 / (1.0f + __expf(-g0));
                    float i1 = u1 * g1 / (1.0f + __expf(-g1));
                    size_t o = ((size_t)e * Tn + r) * In + c;
                    *(uint32_t*)(g_ih + o) = pack2h(i0, i1);
                }
            }
        }
    }
    #undef G1_FILL
}

// ==================== GEMM2: CTA 128x128, warp 32x32, weighted atomic scatter ====================
__global__ __launch_bounds__(512, 2)
void gemm2_kernel(float* __restrict__ out) {
    extern __shared__ char smem[];
    int e = blockIdx.z;
    int n_rows = g_cnt[e];
    int mBase = blockIdx.y * 128;
    if (mBase >= n_rows) return;
    int n0 = blockIdx.x * 128;

    uint32_t sb = smem_u32(smem);
    int tid = threadIdx.x, wid = tid >> 5, lane = tid & 31;
    int wm = wid & 3, wn = wid >> 2;
    int ar = lane & 15, ac = lane >> 4;
    int karow = lane & 15, kacol = lane >> 4;

    int fArow = tid >> 2, fAch = tid & 3;
    const __half* Asrc = g_ih + ((size_t)(e * Tn + mBase + fArow)) * In + fAch * 8;
    uint32_t adst = fArow * A_ROWB + fAch * 16;
    int fBrow = tid >> 4, fBch = tid & 15;
    const __half* Bsrc = g_wdf + ((size_t)e * In + fBrow) * Hn + n0 + fBch * 8;
    uint32_t bdst = A_ARR + fBrow * B2_ROWB + fBch * 16;

    #define G2_FILL(s)                                                         \
        do {                                                                   \
            uint32_t st = sb + ((s) & 3) * G2_STG;                             \
            int k0 = (s) * 32;                                                 \
            cpa16(st + adst, Asrc + k0);                                       \
            cpa16(st + bdst, Bsrc + (size_t)k0 * Hn);                          \
        } while (0)

    float acc[2][4][4] = {{{0}}};

    G2_FILL(0); CP_COMMIT();
    G2_FILL(1); CP_COMMIT();
    G2_FILL(2); CP_COMMIT();

    #pragma unroll 1
    for (int s = 0; s < 32; s++) {
        CP_WAIT2();
        __syncthreads();
        if (s + 3 < 32) G2_FILL(s + 3);
        CP_COMMIT();

        uint32_t aBase = sb + (s & 3) * G2_STG;
        uint32_t bBase = aBase + A_ARR;
        #pragma unroll
        for (int kk = 0; kk < 2; kk++) {
            uint32_t ah[2][4];
            #pragma unroll
            for (int mt = 0; mt < 2; mt++) {
                uint32_t ad = aBase + (uint32_t)(wm * 32 + mt * 16 + ar) * A_ROWB + kk * 32 + ac * 16;
                LDM4(ah[mt], ad);
            }
            uint32_t bh[2][4];
            #pragma unroll
            for (int ng = 0; ng < 2; ng++) {
                uint32_t bd = bBase + (uint32_t)(kk * 16 + karow) * B2_ROWB
                              + wn * 64 + ng * 32 + kacol * 16;
                LDM4T(bh[ng], bd);
            }
            #pragma unroll
            for (int mt = 0; mt < 2; mt++)
                #pragma unroll
                for (int nt = 0; nt < 4; nt++) {
                    int ng = nt >> 1, p = (nt & 1) * 2;
                    MMA(acc[mt][nt], ah[mt], bh[ng][p], bh[ng][p + 1]);
                }
        }
    }

    // epilogue: weighted atomic scatter straight into out
    #pragma unroll
    for (int mt = 0; mt < 2; mt++) {
        #pragma unroll
        for (int h = 0; h < 2; h++) {
            int r = mBase + wm * 32 + mt * 16 + (lane >> 2) + h * 8;
            if (r < n_rows) {
                int tok  = g_stok[e * Tn + r];
                float w  = g_swt [e * Tn + r];
                float* dst = out + (size_t)tok * Hn;
                #pragma unroll
                for (int nt = 0; nt < 4; nt++) {
                    int c = n0 + wn * 32 + nt * 8 + (lane & 3) * 2;
                    atomicAdd(dst + c,     w * acc[mt][nt][h * 2]);
                    atomicAdd(dst + c + 1, w * acc[mt][nt][h * 2 + 1]);
                }
            }
        }
    }
    #undef G2_FILL
}

// ==================== launch ====================
extern "C" void kernel_launch(void* const* d_in, const int* in_sizes, int n_in,
                              void* d_out, int out_size) {
    const float* x  = (const float*)d_in[0];
    const float* Wr = (const float*)d_in[1];
    const float* Wg = (const float*)d_in[2];
    const float* Wu = (const float*)d_in[3];
    const float* Wd = (const float*)d_in[4];
    float* out = (float*)d_out;

    cudaFuncSetAttribute(gemm1_kernel, cudaFuncAttributeMaxDynamicSharedMemorySize, G1_SMEM);
    cudaFuncSetAttribute(gemm2_kernel, cudaFuncAttributeMaxDynamicSharedMemorySize, G2_SMEM);

    // wconv + init fused (zeroes out, counters)
    dim3 wg((En * Hn * In / 4) / 256, 3);
    wconv_kernel<<<wg, 256>>>(Wg, Wu, Wd, out, out_size);

    router_kernel<<<Tn, 256>>>(x, Wr);

    int do_aux = (out_size > Tn * Hn) ? 1 : 0;
    dim3 g1(In / 64, Tn / 128, En);
    gemm1_kernel<<<g1, 512, G1_SMEM>>>(out, do_aux);

    dim3 g2(Hn / 128, Tn / 128, En);
    gemm2_kernel<<<g2, 512, G2_SMEM>>>(out);
}

// round 17
// speedup vs baseline: 1.0364x; 1.0255x over previous
#include <cuda_runtime.h>
#include <cuda_fp16.h>
#include <stdint.h>
#include <math.h>

#define Tn 4096
#define Hn 1024
#define En 8
#define In 1024

// ==================== scratch ====================
__device__ int   g_cnt[En];
__device__ float g_imp[En];
__device__ int   g_stok[En * Tn];     // slot -> token
__device__ float g_swt [En * Tn];     // slot -> combine weight
__device__ __align__(16) __half g_wgf[(size_t)En * Hn * In];
__device__ __align__(16) __half g_wuf[(size_t)En * Hn * In];
__device__ __align__(16) __half g_wdf[(size_t)En * In * Hn];
__device__ __align__(16) __half g_xh[(size_t)Tn * Hn];       // token-ordered fp16 x
__device__ __align__(16) __half g_ih[(size_t)En * Tn * In];

// ==================== helpers ====================
__device__ __forceinline__ uint32_t smem_u32(const void* p) {
    uint32_t a;
    asm("{ .reg .u64 t; cvta.to.shared.u64 t, %1; cvt.u32.u64 %0, t; }" : "=r"(a) : "l"(p));
    return a;
}
__device__ __forceinline__ void cpa16(uint32_t dst, const void* src) {
    asm volatile("cp.async.cg.shared.global [%0], [%1], 16;" :: "r"(dst), "l"(src));
}
#define CP_COMMIT() asm volatile("cp.async.commit_group;" ::: "memory")
#define CP_WAIT2()  asm volatile("cp.async.wait_group 2;" ::: "memory")

#define LDM4(r, addr)                                                          \
    asm volatile("ldmatrix.sync.aligned.m8n8.x4.shared.b16 {%0,%1,%2,%3}, [%4];" \
        : "=r"((r)[0]), "=r"((r)[1]), "=r"((r)[2]), "=r"((r)[3]) : "r"(addr))

#define LDM4T(r, addr)                                                         \
    asm volatile("ldmatrix.sync.aligned.m8n8.x4.trans.shared.b16 {%0,%1,%2,%3}, [%4];" \
        : "=r"((r)[0]), "=r"((r)[1]), "=r"((r)[2]), "=r"((r)[3]) : "r"(addr))

#define MMA(d, a, b0, b1)                                                      \
    asm volatile("mma.sync.aligned.m16n8k16.row.col.f32.f16.f16.f32 "          \
        "{%0,%1,%2,%3}, {%4,%5,%6,%7}, {%8,%9}, {%0,%1,%2,%3};"                \
        : "+f"((d)[0]), "+f"((d)[1]), "+f"((d)[2]), "+f"((d)[3])               \
        : "r"((a)[0]), "r"((a)[1]), "r"((a)[2]), "r"((a)[3]), "r"(b0), "r"(b1))

__device__ __forceinline__ uint32_t pack2h(float a, float b) {
    __half2 H = __floats2half2_rn(a, b);
    return *(uint32_t*)&H;
}

// ==================== init: counters only ====================
__global__ void init_kernel() {
    if (threadIdx.x < En) { g_cnt[threadIdx.x] = 0; g_imp[threadIdx.x] = 0.0f; }
}

// ==================== prep: router (blocks 0..Tn) + wconv/out-zero (rest) ====================
__global__ void prep_kernel(const float* __restrict__ x, const float* __restrict__ Wr,
                            const float* __restrict__ Wg, const float* __restrict__ Wu,
                            const float* __restrict__ Wd,
                            float* __restrict__ out, int out_n) {
    int bid = blockIdx.x;
    if (bid < Tn) {
        // ---- router + token-ordered fp16 cast ----
        int t = bid;
        int warp = threadIdx.x >> 5, lane = threadIdx.x & 31;
        const float* xt = x + (size_t)t * Hn;
        float acc = 0.0f;
        for (int h = lane; h < Hn; h += 32) acc += xt[h] * Wr[h * En + warp];
        #pragma unroll
        for (int o = 16; o > 0; o >>= 1) acc += __shfl_xor_sync(0xffffffff, acc, o);
        __shared__ float logits[En];
        if (lane == 0) logits[warp] = acc;
        __syncthreads();
        if (threadIdx.x == 0) {
            float mx = logits[0];
            #pragma unroll
            for (int e = 1; e < En; e++) mx = fmaxf(mx, logits[e]);
            float p[En], s = 0.0f;
            #pragma unroll
            for (int e = 0; e < En; e++) { p[e] = expf(logits[e] - mx); s += p[e]; }
            float inv = 1.0f / s;
            #pragma unroll
            for (int e = 0; e < En; e++) { p[e] *= inv; atomicAdd(&g_imp[e], p[e]); }
            int i0 = 0;
            #pragma unroll
            for (int e = 1; e < En; e++) if (p[e] > p[i0]) i0 = e;
            int i1 = (i0 == 0) ? 1 : 0;
            #pragma unroll
            for (int e = 0; e < En; e++) if (e != i0 && p[e] > p[i1]) i1 = e;
            float w0 = p[i0], w1 = p[i1];
            float sw = fmaxf(w0 + w1, 1e-9f);
            w0 /= sw; w1 /= sw;
            int p0 = atomicAdd(&g_cnt[i0], 1);
            int p1 = atomicAdd(&g_cnt[i1], 1);
            g_stok[i0 * Tn + p0] = t;  g_swt[i0 * Tn + p0] = w0;
            g_stok[i1 * Tn + p1] = t;  g_swt[i1 * Tn + p1] = w1;
        }
        // cast this token's row once (token-ordered)
        int i = threadIdx.x;
        float4 v = *(const float4*)(xt + i * 4);
        *(uint2*)(g_xh + (size_t)t * Hn + i * 4) =
            make_uint2(pack2h(v.x, v.y), pack2h(v.z, v.w));
    } else {
        // ---- weight cast (+ out zero on z==0 slice) ----
        int w = bid - Tn;
        int z = w >> 13;          // 8192 blocks per matrix
        int xb = w & 8191;
        const float* src = (z == 0) ? Wg : (z == 1) ? Wu : Wd;
        __half* dst = (z == 0) ? g_wgf : (z == 1) ? g_wuf : g_wdf;
        size_t i = ((size_t)xb * 256 + threadIdx.x) * 4;
        float4 v = *(const float4*)(src + i);
        *(uint2*)(dst + i) = make_uint2(pack2h(v.x, v.y), pack2h(v.z, v.w));
        if (z == 0) {
            int t = xb * 256 + threadIdx.x;    // 0..2097151
            int o = t * 2;
            if (o < out_n)     out[o]     = 0.0f;
            if (o + 1 < out_n) out[o + 1] = 0.0f;
            if (t == 0 && out_n > 4194304) out[4194304] = 0.0f;
        }
    }
}

// ==================== smem layout (BK=32, 4-stage cp.async) ====================
#define A_ROWB 80
#define A_ARR (128 * A_ROWB)     // 10240
#define BT_ROWB 144
#define BT_ARR (32 * BT_ROWB)    // 4608
#define B2_ROWB 272
#define B2_ARR (32 * B2_ROWB)    // 8704
#define G1_STG (A_ARR + 2 * BT_ARR)   // 19456
#define G1_SMEM (4 * G1_STG)          // 77824
#define G2_STG (A_ARR + B2_ARR)       // 18944
#define G2_SMEM (4 * G2_STG)          // 75776

// ==================== GEMM1: CTA 128x64(G)+64(U), 16 warps 4x4, warp 32x16 ====================
__global__ __launch_bounds__(512, 2)
void gemm1_kernel(float* __restrict__ out, int do_aux) {
    extern __shared__ char smem[];
    if (do_aux && blockIdx.x == 0 && blockIdx.y == 0 && blockIdx.z == 0 && threadIdx.x == 0) {
        float s = 0.0f;
        #pragma unroll
        for (int e = 0; e < En; e++)
            s += ((float)g_cnt[e] / (float)Tn) * (g_imp[e] / (float)Tn);
        out[Tn * Hn] = (float)En * s * 0.01f;
    }

    int e = blockIdx.z;
    int n_rows = g_cnt[e];
    int mBase = blockIdx.y * 128;
    if (mBase >= n_rows) return;
    int n0 = blockIdx.x * 64;

    uint32_t sb = smem_u32(smem);
    int tid = threadIdx.x, wid = tid >> 5, lane = tid & 31;
    int wm = wid & 3, wn = wid >> 2;
    int ar = lane & 15, ac = lane >> 4;
    int karow = lane & 15, kacol = lane >> 4;

    // A fill: gathered row via slot->token map (one lookup per tile)
    int fArow = tid >> 2, fAch = tid & 3;
    int row = mBase + fArow;
    int tok = g_stok[e * Tn + (row < n_rows ? row : mBase)];
    const __half* Asrc = g_xh + (size_t)tok * Hn + fAch * 8;
    uint32_t adst = fArow * A_ROWB + fAch * 16;
    int isU = tid >= 256;
    int wt = tid & 255;
    int fWrow = wt >> 3, fWch = wt & 7;
    const __half* Wsrc = (isU ? g_wuf : g_wgf) + ((size_t)e * Hn + fWrow) * In + n0 + fWch * 8;
    uint32_t wdst = A_ARR + (isU ? BT_ARR : 0) + fWrow * BT_ROWB + fWch * 16;

    #define G1_FILL(s)                                                         \
        do {                                                                   \
            uint32_t st = sb + ((s) & 3) * G1_STG;                             \
            int k0 = (s) * 32;                                                 \
            cpa16(st + adst, Asrc + k0);                                       \
            cpa16(st + wdst, Wsrc + (size_t)k0 * In);                          \
        } while (0)

    float aG[2][2][4] = {{{0}}}, aU[2][2][4] = {{{0}}};

    G1_FILL(0); CP_COMMIT();
    G1_FILL(1); CP_COMMIT();
    G1_FILL(2); CP_COMMIT();

    #pragma unroll 1
    for (int s = 0; s < 32; s++) {
        CP_WAIT2();
        __syncthreads();
        if (s + 3 < 32) G1_FILL(s + 3);
        CP_COMMIT();

        uint32_t aBase = sb + (s & 3) * G1_STG;
        uint32_t gBase = aBase + A_ARR;
        #pragma unroll
        for (int kk = 0; kk < 2; kk++) {
            uint32_t ah[2][4];
            #pragma unroll
            for (int mt = 0; mt < 2; mt++) {
                uint32_t ad = aBase + (uint32_t)(wm * 32 + mt * 16 + ar) * A_ROWB + kk * 32 + ac * 16;
                LDM4(ah[mt], ad);
            }
            uint32_t bg[4], bu[4];
            {
                uint32_t bd = gBase + (uint32_t)(kk * 16 + karow) * BT_ROWB + wn * 32 + kacol * 16;
                LDM4T(bg, bd);
                LDM4T(bu, bd + BT_ARR);
            }
            #pragma unroll
            for (int mt = 0; mt < 2; mt++)
                #pragma unroll
                for (int nt = 0; nt < 2; nt++) {
                    int p = nt * 2;
                    MMA(aG[mt][nt], ah[mt], bg[p], bg[p + 1]);
                    MMA(aU[mt][nt], ah[mt], bu[p], bu[p + 1]);
                }
        }
    }

    // epilogue: silu(g)*u -> fp16 intermediate
    #pragma unroll
    for (int mt = 0; mt < 2; mt++) {
        #pragma unroll
        for (int nt = 0; nt < 2; nt++) {
            int c = n0 + wn * 16 + nt * 8 + (lane & 3) * 2;
            #pragma unroll
            for (int h = 0; h < 2; h++) {
                int r = mBase + wm * 32 + mt * 16 + (lane >> 2) + h * 8;
                if (r < n_rows) {
                    float g0 = aG[mt][nt][h * 2],     u0 = aU[mt][nt][h * 2];
                    float g1 = aG[mt][nt][h * 2 + 1], u1 = aU[mt][nt][h * 2 + 1];
                    float i0 = u0 * g0 / (1.0f + __expf(-g0));
                    float i1 = u1 * g1 / (1.0f + __expf(-g1));
                    size_t o = ((size_t)e * Tn + r) * In + c;
                    *(uint32_t*)(g_ih + o) = pack2h(i0, i1);
                }
            }
        }
    }
    #undef G1_FILL
}

// ==================== GEMM2: CTA 128x128, warp 32x32, weighted atomic scatter ====================
__global__ __launch_bounds__(512, 2)
void gemm2_kernel(float* __restrict__ out) {
    extern __shared__ char smem[];
    int e = blockIdx.z;
    int n_rows = g_cnt[e];
    int mBase = blockIdx.y * 128;
    if (mBase >= n_rows) return;
    int n0 = blockIdx.x * 128;

    uint32_t sb = smem_u32(smem);
    int tid = threadIdx.x, wid = tid >> 5, lane = tid & 31;
    int wm = wid & 3, wn = wid >> 2;
    int ar = lane & 15, ac = lane >> 4;
    int karow = lane & 15, kacol = lane >> 4;

    int fArow = tid >> 2, fAch = tid & 3;
    const __half* Asrc = g_ih + ((size_t)(e * Tn + mBase + fArow)) * In + fAch * 8;
    uint32_t adst = fArow * A_ROWB + fAch * 16;
    int fBrow = tid >> 4, fBch = tid & 15;
    const __half* Bsrc = g_wdf + ((size_t)e * In + fBrow) * Hn + n0 + fBch * 8;
    uint32_t bdst = A_ARR + fBrow * B2_ROWB + fBch * 16;

    #define G2_FILL(s)                                                         \
        do {                                                                   \
            uint32_t st = sb + ((s) & 3) * G2_STG;                             \
            int k0 = (s) * 32;                                                 \
            cpa16(st + adst, Asrc + k0);                                       \
            cpa16(st + bdst, Bsrc + (size_t)k0 * Hn);                          \
        } while (0)

    float acc[2][4][4] = {{{0}}};

    G2_FILL(0); CP_COMMIT();
    G2_FILL(1); CP_COMMIT();
    G2_FILL(2); CP_COMMIT();

    #pragma unroll 1
    for (int s = 0; s < 32; s++) {
        CP_WAIT2();
        __syncthreads();
        if (s + 3 < 32) G2_FILL(s + 3);
        CP_COMMIT();

        uint32_t aBase = sb + (s & 3) * G2_STG;
        uint32_t bBase = aBase + A_ARR;
        #pragma unroll
        for (int kk = 0; kk < 2; kk++) {
            uint32_t ah[2][4];
            #pragma unroll
            for (int mt = 0; mt < 2; mt++) {
                uint32_t ad = aBase + (uint32_t)(wm * 32 + mt * 16 + ar) * A_ROWB + kk * 32 + ac * 16;
                LDM4(ah[mt], ad);
            }
            uint32_t bh[2][4];
            #pragma unroll
            for (int ng = 0; ng < 2; ng++) {
                uint32_t bd = bBase + (uint32_t)(kk * 16 + karow) * B2_ROWB
                              + wn * 64 + ng * 32 + kacol * 16;
                LDM4T(bh[ng], bd);
            }
            #pragma unroll
            for (int mt = 0; mt < 2; mt++)
                #pragma unroll
                for (int nt = 0; nt < 4; nt++) {
                    int ng = nt >> 1, p = (nt & 1) * 2;
                    MMA(acc[mt][nt], ah[mt], bh[ng][p], bh[ng][p + 1]);
                }
        }
    }

    // epilogue: weighted atomic scatter straight into out
    #pragma unroll
    for (int mt = 0; mt < 2; mt++) {
        #pragma unroll
        for (int h = 0; h < 2; h++) {
            int r = mBase + wm * 32 + mt * 16 + (lane >> 2) + h * 8;
            if (r < n_rows) {
                int tok  = g_stok[e * Tn + r];
                float w  = g_swt [e * Tn + r];
                float* dst = out + (size_t)tok * Hn;
                #pragma unroll
                for (int nt = 0; nt < 4; nt++) {
                    int c = n0 + wn * 32 + nt * 8 + (lane & 3) * 2;
                    atomicAdd(dst + c,     w * acc[mt][nt][h * 2]);
                    atomicAdd(dst + c + 1, w * acc[mt][nt][h * 2 + 1]);
                }
            }
        }
    }
    #undef G2_FILL
}

// ==================== launch ====================
extern "C" void kernel_launch(void* const* d_in, const int* in_sizes, int n_in,
                              void* d_out, int out_size) {
    const float* x  = (const float*)d_in[0];
    const float* Wr = (const float*)d_in[1];
    const float* Wg = (const float*)d_in[2];
    const float* Wu = (const float*)d_in[3];
    const float* Wd = (const float*)d_in[4];
    float* out = (float*)d_out;

    cudaFuncSetAttribute(gemm1_kernel, cudaFuncAttributeMaxDynamicSharedMemorySize, G1_SMEM);
    cudaFuncSetAttribute(gemm2_kernel, cudaFuncAttributeMaxDynamicSharedMemorySize, G2_SMEM);

    init_kernel<<<1, 32>>>();

    // fused prep: router (4096 blocks) + weight cast / out zero (24576 blocks)
    prep_kernel<<<Tn + 3 * 8192, 256>>>(x, Wr, Wg, Wu, Wd, out, out_size);

    int do_aux = (out_size > Tn * Hn) ? 1 : 0;
    dim3 g1(In / 64, Tn / 128, En);
    gemm1_kernel<<<g1, 512, G1_SMEM>>>(out, do_aux);

    dim3 g2(Hn / 128, Tn / 128, En);
    gemm2_kernel<<<g2, 512, G2_SMEM>>>(out);
}